// round 2
// baseline (speedup 1.0000x reference)
#include <cuda_runtime.h>
#include <math.h>

namespace {

constexpr int B  = 128;
constexpr int P  = 196;
constexpr int DE = 2048;   // DENC
constexpr int DD = 512;    // DDEC
constexpr int DA = 512;    // DATT
constexpr int DM = 512;    // DEMB
constexpr int V  = 10000;
constexpr int L  = 21;
constexpr int T  = 20;
constexpr int XK = DM + DE + DD;  // 3072 : x = [emb | gate*ctx | h]
constexpr int G4 = 4 * DD;        // 2048 : i,f,g,o gates
constexpr int KS_G = 6;           // K-split for the big LSTM GEMM

constexpr long long OFF_PRED   = 0;
constexpr long long OFF_ALPHA  = (long long)B * T * V;                  // 25,600,000
constexpr long long OFF_CAPS   = OFF_ALPHA + (long long)B * T * P;     // 26,101,760
constexpr long long OFF_DECLEN = OFF_CAPS + (long long)B * L;          // 26,104,448
constexpr long long OFF_SORT   = OFF_DECLEN + B;                       // 26,104,576

// ---------------- scratch (device globals; no allocation allowed) -----------
__device__ int g_sort[B];
__device__ int g_declen[B];
__device__ int g_caps[B * L];
__device__ __align__(16) float g_enc[(size_t)B * P * DE];     // sorted enc, 205MB
__device__ __align__(16) float g_attn1[(size_t)B * P * DA];   // 51MB
__device__ __align__(16) float g_mean[B * DE];
__device__ __align__(16) float g_h[B * DD];
__device__ __align__(16) float g_c[B * DD];
__device__ __align__(16) float g_hnew[B * DD];
__device__ __align__(16) float g_attn2p[2 * B * DA];
__device__ __align__(16) float g_gatep[2 * B * DE];
__device__ __align__(16) float g_alpha[B * P];
__device__ __align__(16) float g_e[B * P];
__device__ __align__(16) float g_x[B * XK];
__device__ __align__(16) float g_gp[(size_t)KS_G * B * G4];
__device__ __align__(16) float g_Wg[(size_t)XK * G4];         // [W_ih ; W_hh], 25MB

__device__ __forceinline__ float sigm(float x) { return 1.f / (1.f + expf(-x)); }

// ---------------- sort: stable argsort(-lengths) -----------------------------
__global__ void k_sort(const int* __restrict__ cap_len,
                       const int* __restrict__ caps_in,
                       float* __restrict__ out) {
    __shared__ int len[B];
    int i = threadIdx.x;
    len[i] = cap_len[i];
    __syncthreads();
    int li = len[i];
    int pos = 0;
    for (int j = 0; j < B; j++) {
        int lj = len[j];
        pos += (lj > li) || (lj == li && j < i);
    }
    g_sort[pos]   = i;
    g_declen[pos] = li - 1;
    out[OFF_SORT + pos]   = (float)i;
    out[OFF_DECLEN + pos] = (float)(li - 1);
    __syncthreads();
    // gather caps for sorted row i
    int src = g_sort[i];
    for (int l = 0; l < L; l++) {
        int tok = caps_in[src * L + l];
        g_caps[i * L + l] = tok;
        out[OFF_CAPS + (long long)i * L + l] = (float)tok;
    }
}

// ---------------- gather enc into sorted order -------------------------------
__global__ void k_gather(const float* __restrict__ enc) {
    int b = blockIdx.y;
    size_t off = (size_t)blockIdx.x * 1024 + (size_t)threadIdx.x * 4;
    const float4* src = (const float4*)(enc + (size_t)g_sort[b] * P * DE + off);
    float4* dst = (float4*)(g_enc + (size_t)b * P * DE + off);
    *dst = *src;
}

// ---------------- build combined [W_ih; W_hh] --------------------------------
__global__ void k_copyWg(const float* __restrict__ W_ih,
                         const float* __restrict__ W_hh) {
    size_t i = (size_t)blockIdx.x * blockDim.x + threadIdx.x;
    size_t n1 = (size_t)(DM + DE) * G4;      // 2560*2048
    size_t tot = (size_t)XK * G4;
    if (i >= tot) return;
    g_Wg[i] = (i < n1) ? W_ih[i] : W_hh[i - n1];
}

// ---------------- mean over P ------------------------------------------------
__global__ void k_mean() {
    int b = blockIdx.y;
    int d = blockIdx.x * 256 + threadIdx.x;
    const float* e = g_enc + (size_t)b * P * DE + d;
    float s = 0.f;
#pragma unroll 4
    for (int p = 0; p < P; p++) s += e[(size_t)p * DE];
    g_mean[b * DE + d] = s * (1.0f / (float)P);
}

// ---------------- shared GEMM core: 64x64 tile, BK=16, 256 thr, 4x4/thread ---
constexpr int BMt = 64, BNt = 64, BKt = 16;

__device__ __forceinline__ void gemm_core(
    const float* __restrict__ A, const float* __restrict__ Bm,
    int N, int K, int m0, int n0, int k0, int kend,
    float acc[4][4], float* sA, float* sB) {
    int tid = threadIdx.x;
    int ty = tid >> 4, tx = tid & 15;
    int arow = tid >> 2, ak = (tid & 3) << 2;
    int brow = tid >> 4, bc = (tid & 15) << 2;
    for (int kt = k0; kt < kend; kt += BKt) {
        float4 av = *(const float4*)(A + (size_t)(m0 + arow) * K + kt + ak);
        sA[(ak + 0) * BMt + arow] = av.x;
        sA[(ak + 1) * BMt + arow] = av.y;
        sA[(ak + 2) * BMt + arow] = av.z;
        sA[(ak + 3) * BMt + arow] = av.w;
        int col = n0 + bc;
        const float* bp = Bm + (size_t)(kt + brow) * N + col;
        float4 bv;
        if (col + 3 < N) {
            bv = *(const float4*)bp;
        } else {
            bv.x = (col + 0 < N) ? bp[0] : 0.f;
            bv.y = (col + 1 < N) ? bp[1] : 0.f;
            bv.z = (col + 2 < N) ? bp[2] : 0.f;
            bv.w = (col + 3 < N) ? bp[3] : 0.f;
        }
        *(float4*)(sB + brow * BNt + bc) = bv;
        __syncthreads();
#pragma unroll
        for (int kk = 0; kk < BKt; kk++) {
            float4 a4 = *(const float4*)(sA + kk * BMt + ty * 4);
            float4 b4 = *(const float4*)(sB + kk * BNt + tx * 4);
            acc[0][0] += a4.x * b4.x; acc[0][1] += a4.x * b4.y;
            acc[0][2] += a4.x * b4.z; acc[0][3] += a4.x * b4.w;
            acc[1][0] += a4.y * b4.x; acc[1][1] += a4.y * b4.y;
            acc[1][2] += a4.y * b4.z; acc[1][3] += a4.y * b4.w;
            acc[2][0] += a4.z * b4.x; acc[2][1] += a4.z * b4.y;
            acc[2][2] += a4.z * b4.z; acc[2][3] += a4.z * b4.w;
            acc[3][0] += a4.w * b4.x; acc[3][1] += a4.w * b4.y;
            acc[3][2] += a4.w * b4.z; acc[3][3] += a4.w * b4.w;
        }
        __syncthreads();
    }
}

// C = A@B + bias   (grid: x = N/64, y = M/64; M,K multiples of 64/16)
__global__ void k_gemm_bias(const float* __restrict__ A, const float* __restrict__ Bm,
                            const float* __restrict__ bias, float* __restrict__ C,
                            int N, int K) {
    __shared__ float sA[BKt * BMt];
    __shared__ float sB[BKt * BNt];
    float acc[4][4] = {};
    int m0 = blockIdx.y * BMt, n0 = blockIdx.x * BNt;
    gemm_core(A, Bm, N, K, m0, n0, 0, K, acc, sA, sB);
    int ty = threadIdx.x >> 4, tx = threadIdx.x & 15;
#pragma unroll
    for (int i = 0; i < 4; i++) {
        int r = m0 + ty * 4 + i;
        int c0 = n0 + tx * 4;
#pragma unroll
        for (int j = 0; j < 4; j++)
            if (c0 + j < N) C[(size_t)r * N + c0 + j] = acc[i][j] + bias[c0 + j];
    }
}

// part[z] = A@B over K-chunk z   (grid.z = KSPLIT; K % (16*gridDim.z) == 0)
__global__ void k_gemm_part(const float* __restrict__ A, const float* __restrict__ Bm,
                            float* __restrict__ part, int M, int N, int K) {
    __shared__ float sA[BKt * BMt];
    __shared__ float sB[BKt * BNt];
    float acc[4][4] = {};
    int m0 = blockIdx.y * BMt, n0 = blockIdx.x * BNt;
    int z = blockIdx.z;
    int kl = K / gridDim.z;
    gemm_core(A, Bm, N, K, m0, n0, z * kl, (z + 1) * kl, acc, sA, sB);
    int ty = threadIdx.x >> 4, tx = threadIdx.x & 15;
    float* Cz = part + (size_t)z * M * N;
#pragma unroll
    for (int i = 0; i < 4; i++) {
        int r = m0 + ty * 4 + i;
        int c0 = n0 + tx * 4;
        *(float4*)(Cz + (size_t)r * N + c0) = *(float4*)acc[i];
    }
}

// preds = hnew@W_fc + b_fc, masked by active, written straight to d_out
__global__ void k_gemm_preds(const float* __restrict__ A, const float* __restrict__ Bm,
                             const float* __restrict__ bias, float* __restrict__ out,
                             int t) {
    __shared__ float sA[BKt * BMt];
    __shared__ float sB[BKt * BNt];
    float acc[4][4] = {};
    int m0 = blockIdx.y * BMt, n0 = blockIdx.x * BNt;
    gemm_core(A, Bm, V, DD, m0, n0, 0, DD, acc, sA, sB);
    int ty = threadIdx.x >> 4, tx = threadIdx.x & 15;
#pragma unroll
    for (int i = 0; i < 4; i++) {
        int b = m0 + ty * 4 + i;
        int act = (t < g_declen[b]);
        int c0 = n0 + tx * 4;
#pragma unroll
        for (int j = 0; j < 4; j++) {
            int c = c0 + j;
            if (c < V)
                out[OFF_PRED + (size_t)b * T * V + (size_t)t * V + c] =
                    act ? (acc[i][j] + bias[c]) : 0.f;
        }
    }
}

// e[b,p] = sum_k relu(attn1[b,p,k] + attn2[b,k]) * w_f[k] + b_f
// attn2 = attn2p[0] + attn2p[1] + b_da fused in (both partials are L2-resident)
__global__ void k_e(const float* __restrict__ b_da,
                    const float* __restrict__ wf, const float* __restrict__ bf) {
    int bp = blockIdx.x;
    int b = bp / P;
    int tid = threadIdx.x;  // 128
    const float* a1 = g_attn1 + (size_t)bp * DA;
    const float* a2p0 = g_attn2p + b * DA;
    const float* a2p1 = g_attn2p + B * DA + b * DA;
    float s = 0.f;
#pragma unroll 4
    for (int k = tid; k < DA; k += 128) {
        float v = a1[k] + a2p0[k] + a2p1[k] + b_da[k];
        s += fmaxf(v, 0.f) * wf[k];
    }
    __shared__ float red[128];
    red[tid] = s;
    __syncthreads();
    for (int st = 64; st > 0; st >>= 1) {
        if (tid < st) red[tid] += red[tid + st];
        __syncthreads();
    }
    if (tid == 0) g_e[bp] = red[0] + bf[0];
}

// softmax over P per batch; store unmasked alpha to scratch, masked to out
__global__ void k_softmax(float* __restrict__ out, int t) {
    int b = blockIdx.x;
    int tid = threadIdx.x;  // 256
    __shared__ float red[256];
    float v = (tid < P) ? g_e[b * P + tid] : -1e30f;
    red[tid] = v;
    __syncthreads();
    for (int st = 128; st > 0; st >>= 1) {
        if (tid < st) red[tid] = fmaxf(red[tid], red[tid + st]);
        __syncthreads();
    }
    float mx = red[0];
    __syncthreads();
    float ex = (tid < P) ? expf(v - mx) : 0.f;
    red[tid] = ex;
    __syncthreads();
    for (int st = 128; st > 0; st >>= 1) {
        if (tid < st) red[tid] += red[tid + st];
        __syncthreads();
    }
    float inv = 1.f / red[0];
    if (tid < P) {
        float a = ex * inv;
        g_alpha[b * P + tid] = a;
        int act = t < g_declen[b];
        out[OFF_ALPHA + (size_t)b * T * P + (size_t)t * P + tid] = act ? a : 0.f;
    }
}

// ctx + gate fused: x[b, 512+d] = sigmoid(gatep0+gatep1+b_beta) * sum_p enc*alpha
__global__ void k_ctx(const float* __restrict__ b_beta) {
    __shared__ float sa[P];
    int b = blockIdx.y;
    int d = blockIdx.x * 256 + threadIdx.x;
    for (int i = threadIdx.x; i < P; i += 256) sa[i] = g_alpha[b * P + i];
    __syncthreads();
    const float* e = g_enc + (size_t)b * P * DE + d;
    float s = 0.f;
#pragma unroll 4
    for (int p = 0; p < P; p++) s += e[(size_t)p * DE] * sa[p];
    float gt = g_gatep[b * DE + d] + g_gatep[B * DE + b * DE + d] + b_beta[d];
    g_x[(size_t)b * XK + DM + d] = sigm(gt) * s;
}

// x[b,0:512] = emb_table[token]; x[b,2560:3072] = h
__global__ void k_xfill(const float* __restrict__ emb, int t) {
    int b = blockIdx.y;
    int i = blockIdx.x * 256 + threadIdx.x;  // 0..1023
    if (i < DM) {
        int tok = g_caps[b * L + t];
        g_x[(size_t)b * XK + i] = emb[(size_t)tok * DM + i];
    } else {
        int j = i - DM;
        g_x[(size_t)b * XK + DM + DE + j] = g_h[b * DD + j];
    }
}

// LSTM cell: reduce KS_G partials + biases, nonlinearity, masked state update
__global__ void k_lstm(const float* __restrict__ b_ih, const float* __restrict__ b_hh,
                       int t) {
    int idx = blockIdx.x * blockDim.x + threadIdx.x;  // B*DD
    int b = idx >> 9, j = idx & 511;
    float gi = b_ih[j] + b_hh[j];
    float gf = b_ih[DD + j] + b_hh[DD + j];
    float gg = b_ih[2 * DD + j] + b_hh[2 * DD + j];
    float go = b_ih[3 * DD + j] + b_hh[3 * DD + j];
#pragma unroll
    for (int s = 0; s < KS_G; s++) {
        const float* gp = g_gp + ((size_t)s * B + b) * G4;
        gi += gp[j];
        gf += gp[DD + j];
        gg += gp[2 * DD + j];
        go += gp[3 * DD + j];
    }
    float c_old = g_c[idx];
    float cn = sigm(gf) * c_old + sigm(gi) * tanhf(gg);
    float hn = sigm(go) * tanhf(cn);
    g_hnew[idx] = hn;
    if (t < g_declen[b]) {
        g_h[idx] = hn;
        g_c[idx] = cn;
    }
}

}  // namespace

extern "C" void kernel_launch(void* const* d_in, const int* in_sizes, int n_in,
                              void* d_out, int out_size) {
    const float* enc    = (const float*)d_in[0];
    const int*   caps   = (const int*)d_in[1];
    const int*   clen   = (const int*)d_in[2];
    const float* W_ea   = (const float*)d_in[3];
    const float* b_ea   = (const float*)d_in[4];
    const float* W_da   = (const float*)d_in[5];
    const float* b_da   = (const float*)d_in[6];
    const float* w_f    = (const float*)d_in[7];
    const float* b_f    = (const float*)d_in[8];
    const float* emb    = (const float*)d_in[9];
    const float* W_ih   = (const float*)d_in[10];
    const float* b_ih   = (const float*)d_in[11];
    const float* W_hh   = (const float*)d_in[12];
    const float* b_hh   = (const float*)d_in[13];
    const float* W_hd   = (const float*)d_in[14];
    const float* b_hd   = (const float*)d_in[15];
    const float* W_cd   = (const float*)d_in[16];
    const float* b_cd   = (const float*)d_in[17];
    const float* W_beta = (const float*)d_in[18];
    const float* b_beta = (const float*)d_in[19];
    const float* W_fc   = (const float*)d_in[20];
    const float* b_fc   = (const float*)d_in[21];
    float* out = (float*)d_out;

    float *p_enc, *p_attn1, *p_mean, *p_h, *p_c, *p_hnew;
    float *p_attn2p, *p_gatep, *p_x, *p_gp, *p_Wg;
    cudaGetSymbolAddress((void**)&p_enc, g_enc);
    cudaGetSymbolAddress((void**)&p_attn1, g_attn1);
    cudaGetSymbolAddress((void**)&p_mean, g_mean);
    cudaGetSymbolAddress((void**)&p_h, g_h);
    cudaGetSymbolAddress((void**)&p_c, g_c);
    cudaGetSymbolAddress((void**)&p_hnew, g_hnew);
    cudaGetSymbolAddress((void**)&p_attn2p, g_attn2p);
    cudaGetSymbolAddress((void**)&p_gatep, g_gatep);
    cudaGetSymbolAddress((void**)&p_x, g_x);
    cudaGetSymbolAddress((void**)&p_gp, g_gp);
    cudaGetSymbolAddress((void**)&p_Wg, g_Wg);

    // ---- setup ----
    k_sort<<<1, B>>>(clen, caps, out);
    k_gather<<<dim3(P * DE / 1024, B), 256>>>(enc);
    {
        size_t tot = (size_t)XK * G4;
        k_copyWg<<<(unsigned)((tot + 1023) / 1024), 1024>>>(W_ih, W_hh);
    }
    k_mean<<<dim3(DE / 256, B), 256>>>();
    // h0 = mean@W_hd + b_hd ; c0 = mean@W_cd + b_cd
    k_gemm_bias<<<dim3(DD / BNt, B / BMt), 256>>>(p_mean, W_hd, b_hd, p_h, DD, DE);
    k_gemm_bias<<<dim3(DD / BNt, B / BMt), 256>>>(p_mean, W_cd, b_cd, p_c, DD, DE);
    // attn1 = enc_sorted @ W_ea + b_ea   (M = 25088)
    k_gemm_bias<<<dim3(DA / BNt, (B * P) / BMt), 256>>>(p_enc, W_ea, b_ea, p_attn1, DA, DE);

    // ---- time loop ----
    for (int t = 0; t < T; t++) {
        k_gemm_part<<<dim3(DA / BNt, B / BMt, 2), 256>>>(p_h, W_da, p_attn2p, B, DA, DD);
        k_gemm_part<<<dim3(DE / BNt, B / BMt, 2), 256>>>(p_h, W_beta, p_gatep, B, DE, DD);
        k_e<<<B * P, 128>>>(b_da, w_f, b_f);
        k_softmax<<<B, 256>>>(out, t);
        k_ctx<<<dim3(DE / 256, B), 256>>>(b_beta);
        k_xfill<<<dim3(4, B), 256>>>(emb, t);
        k_gemm_part<<<dim3(G4 / BNt, B / BMt, KS_G), 256>>>(p_x, p_Wg, p_gp, B, G4, XK);
        k_lstm<<<B * DD / 256, 256>>>(b_ih, b_hh, t);
        k_gemm_preds<<<dim3((V + BNt - 1) / BNt, B / BMt), 256>>>(p_hnew, W_fc, b_fc, out, t);
    }
}